// round 1
// baseline (speedup 1.0000x reference)
#include <cuda_runtime.h>

// DyDepthwiseConvAtten: B=1024, N=100, C=256, K=3
// out[b,n,c] = LN_c( w0*v[c-1] + w1*v[c] + w2*v[c+1] ),  w_k = q[b,n,:]·W_w[k,:] + b_w[k]
//
// One warp per row (102400 rows). 8 channels/thread as 2x float4.
// Conv halo via warp shuffles; all reductions via shfl_xor butterflies.
// Pure fp32, HBM-bound (~315 MB traffic).

#define ROWS_TOTAL (1024 * 100)
#define CH 256
#define LN_EPS 1e-5f

__global__ __launch_bounds__(256)
void dydw_conv_ln_kernel(const float* __restrict__ query,
                         const float* __restrict__ value,
                         const float* __restrict__ W_w,
                         const float* __restrict__ b_w,
                         const float* __restrict__ gamma,
                         const float* __restrict__ beta,
                         float* __restrict__ out)
{
    const int lane   = threadIdx.x & 31;
    const int warp   = (blockIdx.x * blockDim.x + threadIdx.x) >> 5;
    const int nwarps = (gridDim.x * blockDim.x) >> 5;
    const int cbase  = lane * 8;

    // Per-channel constants live in registers across the row loop.
    float w0r[8], w1r[8], w2r[8], gr[8], br[8];
    #pragma unroll
    for (int i = 0; i < 8; i++) {
        w0r[i] = __ldg(&W_w[0 * CH + cbase + i]);
        w1r[i] = __ldg(&W_w[1 * CH + cbase + i]);
        w2r[i] = __ldg(&W_w[2 * CH + cbase + i]);
        gr[i]  = __ldg(&gamma[cbase + i]);
        br[i]  = __ldg(&beta[cbase + i]);
    }
    const float bw0 = __ldg(&b_w[0]);
    const float bw1 = __ldg(&b_w[1]);
    const float bw2 = __ldg(&b_w[2]);

    for (int row = warp; row < ROWS_TOTAL; row += nwarps) {
        const float4* qrow = (const float4*)(query + (size_t)row * CH);
        const float4* vrow = (const float4*)(value + (size_t)row * CH);
        const float4 q0 = qrow[lane * 2 + 0];
        const float4 q1 = qrow[lane * 2 + 1];
        const float4 v0 = vrow[lane * 2 + 0];
        const float4 v1 = vrow[lane * 2 + 1];
        const float q[8] = {q0.x, q0.y, q0.z, q0.w, q1.x, q1.y, q1.z, q1.w};
        const float v[8] = {v0.x, v0.y, v0.z, v0.w, v1.x, v1.y, v1.z, v1.w};

        // Dynamic 3-tap kernel: w_k = q . W_w[k] + b_w[k]
        float s0 = 0.f, s1 = 0.f, s2 = 0.f;
        #pragma unroll
        for (int i = 0; i < 8; i++) {
            s0 = fmaf(q[i], w0r[i], s0);
            s1 = fmaf(q[i], w1r[i], s1);
            s2 = fmaf(q[i], w2r[i], s2);
        }
        #pragma unroll
        for (int off = 16; off; off >>= 1) {
            s0 += __shfl_xor_sync(0xffffffffu, s0, off);
            s1 += __shfl_xor_sync(0xffffffffu, s1, off);
            s2 += __shfl_xor_sync(0xffffffffu, s2, off);
        }
        const float k0 = s0 + bw0;
        const float k1 = s1 + bw1;
        const float k2 = s2 + bw2;

        // Halo exchange for the 3-tap conv (zero padding at row edges).
        float left  = __shfl_up_sync(0xffffffffu, v[7], 1);
        float right = __shfl_down_sync(0xffffffffu, v[0], 1);
        if (lane == 0)  left = 0.f;
        if (lane == 31) right = 0.f;

        float o[8];
        #pragma unroll
        for (int i = 0; i < 8; i++) {
            const float vm = (i == 0) ? left  : v[i - 1];
            const float vp = (i == 7) ? right : v[i + 1];
            o[i] = fmaf(k0, vm, fmaf(k1, v[i], k2 * vp));
        }

        // LayerNorm over 256 channels: E[x], E[x^2] via butterfly reduce.
        float sum = 0.f, sq = 0.f;
        #pragma unroll
        for (int i = 0; i < 8; i++) {
            sum += o[i];
            sq = fmaf(o[i], o[i], sq);
        }
        #pragma unroll
        for (int off = 16; off; off >>= 1) {
            sum += __shfl_xor_sync(0xffffffffu, sum, off);
            sq  += __shfl_xor_sync(0xffffffffu, sq, off);
        }
        const float mean = sum * (1.f / CH);
        const float var  = sq * (1.f / CH) - mean * mean;
        const float rstd = rsqrtf(var + LN_EPS);

        float y[8];
        #pragma unroll
        for (int i = 0; i < 8; i++)
            y[i] = fmaf((o[i] - mean) * rstd, gr[i], br[i]);

        float4* orow = (float4*)(out + (size_t)row * CH);
        orow[lane * 2 + 0] = make_float4(y[0], y[1], y[2], y[3]);
        orow[lane * 2 + 1] = make_float4(y[4], y[5], y[6], y[7]);
    }
}

extern "C" void kernel_launch(void* const* d_in, const int* in_sizes, int n_in,
                              void* d_out, int out_size)
{
    const float* query = (const float*)d_in[0];
    const float* value = (const float*)d_in[1];
    const float* W_w   = (const float*)d_in[2];
    const float* b_w   = (const float*)d_in[3];
    const float* gamma = (const float*)d_in[4];
    const float* beta  = (const float*)d_in[5];
    float* out = (float*)d_out;

    // 1600 blocks x 8 warps = 12800 warps -> exactly 8 rows per warp.
    dydw_conv_ln_kernel<<<1600, 256>>>(query, value, W_w, b_w, gamma, beta, out);
}

// round 2
// speedup vs baseline: 1.1629x; 1.1629x over previous
#include <cuda_runtime.h>

// DyDepthwiseConvAtten: B=1024, N=100, C=256, K=3
// Split into two kernels:
//   K1: w[row] = (q[row]·W_w[k] + b_w[k]) for k=0..2  -> g_w (float4-padded)
//   K2: out[row,c] = LN_c( w0*v[c-1] + w1*v[c] + w2*v[c+1] )
// Warp per row, 8 ch/thread (2x float4). Grouped butterfly reductions to
// minimize SHFL count (L1/LSU was the R1 bottleneck at 77%).

#define ROWS_TOTAL (1024 * 100)
#define CH 256
#define LN_EPS 1e-5f

// scratch for per-row conv taps (k0,k1,k2,unused) — 1.6 MB, L2-resident
__device__ float4 g_w[ROWS_TOTAL];

// ---------------- kernel 1: dynamic tap computation ----------------
__global__ __launch_bounds__(256, 4)
void dydw_wcalc_kernel(const float* __restrict__ query,
                       const float* __restrict__ W_w,
                       const float* __restrict__ b_w)
{
    const int lane   = threadIdx.x & 31;
    const int warp   = (blockIdx.x * blockDim.x + threadIdx.x) >> 5;
    const int nwarps = (gridDim.x * blockDim.x) >> 5;
    const int cbase  = lane * 8;
    const int grp    = lane >> 3;   // 0..3 : which tap this lane-group finishes

    float w0r[8], w1r[8], w2r[8];
    #pragma unroll
    for (int i = 0; i < 8; i++) {
        w0r[i] = __ldg(&W_w[0 * CH + cbase + i]);
        w1r[i] = __ldg(&W_w[1 * CH + cbase + i]);
        w2r[i] = __ldg(&W_w[2 * CH + cbase + i]);
    }
    // bias for this lane's assigned tap (group 3 is spare -> 0)
    const float bias = (grp < 3) ? __ldg(&b_w[grp]) : 0.0f;

    for (int row = warp; row < ROWS_TOTAL; row += nwarps) {
        const float4* qrow = (const float4*)(query + (size_t)row * CH);
        const float4 q0 = qrow[lane * 2 + 0];
        const float4 q1 = qrow[lane * 2 + 1];
        const float q[8] = {q0.x, q0.y, q0.z, q0.w, q1.x, q1.y, q1.z, q1.w};

        float s0 = 0.f, s1 = 0.f, s2 = 0.f;
        #pragma unroll
        for (int i = 0; i < 8; i++) {
            s0 = fmaf(q[i], w0r[i], s0);
            s1 = fmaf(q[i], w1r[i], s1);
            s2 = fmaf(q[i], w2r[i], s2);
        }
        // butterfly offsets 16,8 on all three -> every lane holds the
        // partial sum of its mod-8 lane class for each value
        #pragma unroll
        for (int off = 16; off >= 8; off >>= 1) {
            s0 += __shfl_xor_sync(0xffffffffu, s0, off);
            s1 += __shfl_xor_sync(0xffffffffu, s1, off);
            s2 += __shfl_xor_sync(0xffffffffu, s2, off);
        }
        // each 8-lane group finishes one value (offsets 4,2,1 stay in-group,
        // and all lanes of a group carry the same logical value)
        float t = (grp == 0) ? s0 : (grp == 1) ? s1 : (grp == 2) ? s2 : s0;
        #pragma unroll
        for (int off = 4; off; off >>= 1)
            t += __shfl_xor_sync(0xffffffffu, t, off);

        // lanes 0,8,16 hold full s0,s1,s2; lane 24 writes the pad.
        if ((lane & 7) == 0) {
            float val = (grp < 3) ? (t + bias) : 0.0f;
            ((float*)&g_w[row])[grp] = val;   // 4 lanes, one 16B sector
        }
    }
}

// ---------------- kernel 2: conv + LayerNorm ----------------
__global__ __launch_bounds__(256, 4)
void dydw_conv_ln_kernel(const float* __restrict__ value,
                         const float* __restrict__ gamma,
                         const float* __restrict__ beta,
                         float* __restrict__ out)
{
    const int lane   = threadIdx.x & 31;
    const int warp   = (blockIdx.x * blockDim.x + threadIdx.x) >> 5;
    const int nwarps = (gridDim.x * blockDim.x) >> 5;
    const int cbase  = lane * 8;

    float gr[8], br[8];
    #pragma unroll
    for (int i = 0; i < 8; i++) {
        gr[i] = __ldg(&gamma[cbase + i]);
        br[i] = __ldg(&beta[cbase + i]);
    }

    for (int row = warp; row < ROWS_TOTAL; row += nwarps) {
        const float4 w4 = __ldg(&g_w[row]);   // uniform: 1 wavefront (L2 hit)
        const float k0 = w4.x, k1 = w4.y, k2 = w4.z;

        const float4* vrow = (const float4*)(value + (size_t)row * CH);
        const float4 v0 = vrow[lane * 2 + 0];
        const float4 v1 = vrow[lane * 2 + 1];
        const float v[8] = {v0.x, v0.y, v0.z, v0.w, v1.x, v1.y, v1.z, v1.w};

        // halo for the 3-tap conv (zero pad at row edges)
        float left  = __shfl_up_sync(0xffffffffu, v[7], 1);
        float right = __shfl_down_sync(0xffffffffu, v[0], 1);
        if (lane == 0)  left = 0.f;
        if (lane == 31) right = 0.f;

        float o[8];
        float sum = 0.f, sq = 0.f;
        #pragma unroll
        for (int i = 0; i < 8; i++) {
            const float vm = (i == 0) ? left  : v[i - 1];
            const float vp = (i == 7) ? right : v[i + 1];
            o[i] = fmaf(k0, vm, fmaf(k1, v[i], k2 * vp));
            sum += o[i];
            sq = fmaf(o[i], o[i], sq);
        }

        // grouped 2-value reduce: offset 16, then halves finish different values
        const float a = sum + __shfl_xor_sync(0xffffffffu, sum, 16);
        const float b = sq  + __shfl_xor_sync(0xffffffffu, sq,  16);
        float t = (lane < 16) ? a : b;
        #pragma unroll
        for (int off = 8; off; off >>= 1)
            t += __shfl_xor_sync(0xffffffffu, t, off);
        const float tot_sum = __shfl_sync(0xffffffffu, t, 0);
        const float tot_sq  = __shfl_sync(0xffffffffu, t, 16);

        const float mean = tot_sum * (1.f / CH);
        const float var  = tot_sq * (1.f / CH) - mean * mean;
        const float rstd = rsqrtf(var + LN_EPS);

        float y[8];
        #pragma unroll
        for (int i = 0; i < 8; i++)
            y[i] = fmaf((o[i] - mean) * rstd, gr[i], br[i]);

        float4* orow = (float4*)(out + (size_t)row * CH);
        orow[lane * 2 + 0] = make_float4(y[0], y[1], y[2], y[3]);
        orow[lane * 2 + 1] = make_float4(y[4], y[5], y[6], y[7]);
    }
}

extern "C" void kernel_launch(void* const* d_in, const int* in_sizes, int n_in,
                              void* d_out, int out_size)
{
    const float* query = (const float*)d_in[0];
    const float* value = (const float*)d_in[1];
    const float* W_w   = (const float*)d_in[2];
    const float* b_w   = (const float*)d_in[3];
    const float* gamma = (const float*)d_in[4];
    const float* beta  = (const float*)d_in[5];
    float* out = (float*)d_out;

    // 1600 blocks x 8 warps = 12800 warps -> 8 rows per warp
    dydw_wcalc_kernel<<<1600, 256>>>(query, W_w, b_w);
    dydw_conv_ln_kernel<<<1600, 256>>>(value, gamma, beta, out);
}